// round 9
// baseline (speedup 1.0000x reference)
#include <cuda_runtime.h>
#include <cstdint>

// MAM dense: C[m,n] = max_k(A[m,k]*W[n,k]) + min_k(A[m,k]*W[n,k]) + bias[n]
// A:[M,K], W:[N,K], bias:[N], C:[M,N], fp32. M=2048, K=1024, N=1024.
//
// alu-pipe (FMNMX) floor = 112us; R7 measured 57% issue with no pipe >63%
// -> stall bound. This round: 3-stage cp.async ring + wait_group 1 so the
// per-k-block wait retires instantly; only the barrier remains. f32x2 packed
// multiplies kept (halves mul issue slots; movs verified elided in R7).

#define BM 64
#define BN 32
#define BK 32
#define PAD 36    // floats per smem row = 144B = 9 x 16B (odd -> conflict-free)
#define NT 128
#define NSTAGE 3

__device__ __forceinline__ unsigned long long mul2(unsigned long long a,
                                                   unsigned long long b) {
    unsigned long long r;
    asm("mul.rn.f32x2 %0, %1, %2;" : "=l"(r) : "l"(a), "l"(b));
    return r;
}

__device__ __forceinline__ void unpack2(unsigned long long d, float& lo, float& hi) {
    asm("mov.b64 {%0, %1}, %2;" : "=f"(lo), "=f"(hi) : "l"(d));
}

__global__ __launch_bounds__(NT, 5)
void mam_dense_kernel(const float* __restrict__ A,
                      const float* __restrict__ W,
                      const float* __restrict__ bias,
                      float* __restrict__ C,
                      int M, int N, int K) {
    __shared__ float As[NSTAGE][BM * PAD];
    __shared__ float Bs[NSTAGE][BN * PAD];

    const int t  = threadIdx.x;
    const int tx = t & 7;     // n-direction (8)
    const int ty = t >> 3;    // m-direction (16)

    const int rowBase = blockIdx.y * BM;
    const int colBase = blockIdx.x * BN;

    // cp.async mapping
    const int lrow = t >> 3;        // 0..15
    const int lq   = (t & 7) * 4;   // float offset within row: 0,4,...,28

    const float* aG = A + (size_t)(rowBase + lrow) * K + lq;
    const float* bG = W + (size_t)(colBase + lrow) * K + lq;

    uint32_t asB[NSTAGE], bsB[NSTAGE];
#pragma unroll
    for (int s = 0; s < NSTAGE; ++s) {
        asB[s] = (uint32_t)__cvta_generic_to_shared(&As[s][0]);
        bsB[s] = (uint32_t)__cvta_generic_to_shared(&Bs[s][0]);
    }
    const uint32_t sOff = (uint32_t)(lrow * PAD + lq) * 4u;

#define LOAD_BLOCK(KB, STG)                                                          \
    do {                                                                             \
        const float* a0 = aG + (KB) * BK;                                            \
        const float* b0 = bG + (KB) * BK;                                            \
        uint32_t ad = asB[STG] + sOff;                                               \
        uint32_t bd = bsB[STG] + sOff;                                               \
        _Pragma("unroll")                                                            \
        for (int i = 0; i < 4; ++i)                                                  \
            asm volatile("cp.async.cg.shared.global [%0], [%1], 16;\n" ::            \
                         "r"(ad + (uint32_t)(i * 16 * PAD * 4)),                     \
                         "l"(a0 + (size_t)i * 16 * K));                              \
        _Pragma("unroll")                                                            \
        for (int i = 0; i < 2; ++i)                                                  \
            asm volatile("cp.async.cg.shared.global [%0], [%1], 16;\n" ::            \
                         "r"(bd + (uint32_t)(i * 16 * PAD * 4)),                     \
                         "l"(b0 + (size_t)i * 16 * K));                              \
        asm volatile("cp.async.commit_group;\n");                                    \
    } while (0)

    float mx[4][4], mn[4][4];
#pragma unroll
    for (int i = 0; i < 4; ++i)
#pragma unroll
        for (int j = 0; j < 4; ++j) {
            mx[i][j] = -3.402823466e38f;
            mn[i][j] =  3.402823466e38f;
        }

    const int NKB = K / BK;

    // prologue: fill 2 of 3 stages
    LOAD_BLOCK(0, 0);
    LOAD_BLOCK(1, 1);

    int stage = 0;
    for (int kb = 0; kb < NKB; ++kb) {
        // oldest outstanding group (this stage) must be complete; it was
        // issued 2 blocks ago so this retires with no stall.
        asm volatile("cp.async.wait_group 1;\n" ::: "memory");
        __syncthreads();

        // refill the stage we finished reading last iteration
        if (kb + 2 < NKB) {
            int ns = stage + 2;
            if (ns >= NSTAGE) ns -= NSTAGE;
            LOAD_BLOCK(kb + 2, ns);
        } else {
            // keep the group count in sync so wait_group 1 semantics hold
            asm volatile("cp.async.commit_group;\n");
        }

        const float* as = As[stage];
        const float* bs = Bs[stage];
#pragma unroll
        for (int kq = 0; kq < BK / 4; ++kq) {
            // each ulonglong2 = 4 consecutive k-values as two packed f32 pairs
            ulonglong2 av[4], bv[4];
#pragma unroll
            for (int i = 0; i < 4; ++i)
                av[i] = *(const ulonglong2*)(as + (ty * 4 + i) * PAD + kq * 4);
#pragma unroll
            for (int j = 0; j < 4; ++j)
                bv[j] = *(const ulonglong2*)(bs + (tx + 8 * j) * PAD + kq * 4);
#pragma unroll
            for (int i = 0; i < 4; ++i) {
#pragma unroll
                for (int j = 0; j < 4; ++j) {
                    unsigned long long d0 = mul2(av[i].x, bv[j].x);  // p(k0), p(k1)
                    unsigned long long d1 = mul2(av[i].y, bv[j].y);  // p(k2), p(k3)
                    float p0, p1, p2, p3;
                    unpack2(d0, p0, p1);
                    unpack2(d1, p2, p3);
                    mx[i][j] = fmaxf(mx[i][j], p0); mn[i][j] = fminf(mn[i][j], p0);
                    mx[i][j] = fmaxf(mx[i][j], p1); mn[i][j] = fminf(mn[i][j], p1);
                    mx[i][j] = fmaxf(mx[i][j], p2); mn[i][j] = fminf(mn[i][j], p2);
                    mx[i][j] = fmaxf(mx[i][j], p3); mn[i][j] = fminf(mn[i][j], p3);
                }
            }
        }

        stage = stage + 1;
        if (stage == NSTAGE) stage = 0;
    }

    // epilogue: C = mx + mn + bias
    float bb[4];
#pragma unroll
    for (int j = 0; j < 4; ++j)
        bb[j] = bias[colBase + tx + 8 * j];

#pragma unroll
    for (int i = 0; i < 4; ++i) {
        const size_t rowOff = (size_t)(rowBase + ty * 4 + i) * N + colBase;
#pragma unroll
        for (int j = 0; j < 4; ++j)
            C[rowOff + tx + 8 * j] = mx[i][j] + mn[i][j] + bb[j];
    }
#undef LOAD_BLOCK
}

extern "C" void kernel_launch(void* const* d_in, const int* in_sizes, int n_in,
                              void* d_out, int out_size) {
    const float* x      = (const float*)d_in[0];   // [M, K]
    const float* weight = (const float*)d_in[1];   // [N, K]
    const float* bias   = (const float*)d_in[2];   // [N]
    float* out          = (float*)d_out;           // [M, N]

    const int N = in_sizes[2];
    const int K = in_sizes[1] / N;
    const int M = in_sizes[0] / K;

    dim3 grid(N / BN, M / BM);   // (32, 32) = 1024 CTAs -> ~6.9 per SM
    mam_dense_kernel<<<grid, NT>>>(x, weight, bias, out, M, N, K);
}